// round 5
// baseline (speedup 1.0000x reference)
#include <cuda_runtime.h>
#include <stdint.h>

#define SEQ    2048
#define BITS   256
#define HEADS  8
#define NBPN   12
#define MAXD   8
#define NT     1024
#define GRID_MAIN 152

// Scratch (device globals -- no allocation allowed)
__device__ uint32_t       g_tok[SEQ * 8];        // packed token bits, 32B/row
__device__ unsigned short g_Ak[SEQ * 8];         // per-row key-address parts
__device__ unsigned short g_Aq[SEQ * 8];         // per-row query-address parts
__device__ unsigned char  g_tabB[HEADS * 4096];  // table as bytes
__device__ short          g_Ar[(MAXD + 1) * HEADS];

// ---------------------------------------------------------------------------
// Precompute (warp-per-row): ballot-pack token bits, build Aq/Ak per row,
// Ar per distance, table floats -> bytes.
// ---------------------------------------------------------------------------
__global__ void pre_kernel(const int* __restrict__ tokens,
                           const int* __restrict__ head_idx,
                           const float* __restrict__ table) {
    int tid = blockIdx.x * blockDim.x + threadIdx.x;

    if (tid < HEADS * 4096)
        g_tabB[tid] = (table[tid] > 0.5f) ? (unsigned char)1 : (unsigned char)0;

    if (tid < (MAXD + 1) * HEADS) {
        int d = tid / HEADS, h = tid % HEADS;
        int ar = 0;
        for (int k = 0; k < NBPN; k++) {
            int idx = head_idx[h * NBPN + k];
            if (idx >= 2 * BITS) {
                int p = idx - 2 * BITS;
                if (p > 3) p = 3;
                ar |= ((d >> p) & 1) << k;
            }
        }
        g_Ar[d * HEADS + h] = (short)ar;
    }

    int row  = tid >> 5;
    int lane = tid & 31;
    if (row < SEQ) {
        uint32_t w[8];
        #pragma unroll
        for (int q = 0; q < 8; q++) {
            int v = tokens[row * BITS + q * 32 + lane];
            w[q] = __ballot_sync(0xFFFFFFFFu, v & 1);   // all lanes get the word
        }
        if (lane < 8) {
            g_tok[row * 8 + lane] = w[lane];
            int h = lane;
            int aq = 0, ak = 0;
            for (int k = 0; k < NBPN; k++) {
                int idx = head_idx[h * NBPN + k];
                if (idx < BITS) {
                    aq |= (int)((w[idx >> 5] >> (idx & 31)) & 1u) << k;
                } else if (idx < 2 * BITS) {
                    int i2 = idx - BITS;
                    ak |= (int)((w[i2 >> 5] >> (i2 & 31)) & 1u) << k;
                }
            }
            g_Aq[row * 8 + h] = (unsigned short)aq;
            g_Ak[row * 8 + h] = (unsigned short)ak;
        }
    }
}

// ---------------------------------------------------------------------------
// Main: persistent CTAs, TWO WARPS PER ROW (even/odd j-halves, stride 64).
// Whole working set in SMEM. One __syncthreads total to merge pair partials.
// ---------------------------------------------------------------------------
__global__ __launch_bounds__(NT, 1)
void main_kernel(float* __restrict__ out) {
    extern __shared__ unsigned char smem[];
    unsigned char* sTab   = smem;                      // 32768 B
    uint4*         sAk4   = (uint4*)(smem + 32768);    // 32768 B
    uint4*         sTokLo = (uint4*)(smem + 65536);    // 32768 B (words 0..3)
    uint4*         sTokHi = (uint4*)(smem + 98304);    // 32768 B (words 4..7)
    int*           sArD   = (int*)(smem + 131072);     // 72 ints: Ar[d]-Ar[8]
    uint32_t*      sRed   = (uint32_t*)(smem + 131072 + 128 * 4); // 32 warps x 10

    const int tid = threadIdx.x;

    // Stage working set into SMEM once per block
    {
        const uint4* g1 = (const uint4*)g_tabB;
        uint4* s1 = (uint4*)sTab;
        for (int x = tid; x < 2048; x += NT) s1[x] = g1[x];
        const uint4* g2 = (const uint4*)g_Ak;
        for (int x = tid; x < 2048; x += NT) sAk4[x] = g2[x];
        const uint4* g3 = (const uint4*)g_tok;
        for (int x = tid; x < 4096; x += NT) {
            uint4 v = g3[x];
            if (x & 1) sTokHi[x >> 1] = v; else sTokLo[x >> 1] = v;
        }
        if (tid < (MAXD + 1) * HEADS)
            sArD[tid] = (int)g_Ar[tid] - (int)g_Ar[MAXD * HEADS + (tid & 7)];
    }
    __syncthreads();

    const int lane = tid & 31, wid = tid >> 5;
    const int pair = wid >> 1, sub = wid & 1;
    const int i = pair * GRID_MAIN + (int)blockIdx.x;   // one row per warp PAIR
    const bool active = (i < SEQ);

    uint32_t a0 = 0, a1 = 0, a2 = 0, a3 = 0, a4 = 0, a5 = 0, a6 = 0, a7 = 0;
    int cnt = 0;
    int kmax = -1;

    if (active) {
        int off0 = 0 * 4096 + (int)g_Aq[i * 8 + 0] + (int)g_Ar[MAXD * HEADS + 0];
        int off1 = 1 * 4096 + (int)g_Aq[i * 8 + 1] + (int)g_Ar[MAXD * HEADS + 1];
        int off2 = 2 * 4096 + (int)g_Aq[i * 8 + 2] + (int)g_Ar[MAXD * HEADS + 2];
        int off3 = 3 * 4096 + (int)g_Aq[i * 8 + 3] + (int)g_Ar[MAXD * HEADS + 3];
        int off4 = 4 * 4096 + (int)g_Aq[i * 8 + 4] + (int)g_Ar[MAXD * HEADS + 4];
        int off5 = 5 * 4096 + (int)g_Aq[i * 8 + 5] + (int)g_Ar[MAXD * HEADS + 5];
        int off6 = 6 * 4096 + (int)g_Aq[i * 8 + 6] + (int)g_Ar[MAXD * HEADS + 6];
        int off7 = 7 * 4096 + (int)g_Aq[i * 8 + 7] + (int)g_Ar[MAXD * HEADS + 7];

        #pragma unroll 2
        for (int j = lane + 32 * sub; j <= i; j += 64) {
            uint4 akv = sAk4[j];
            int o0 = off0 + (int)(akv.x & 0xFFFFu);
            int o1 = off1 + (int)(akv.x >> 16);
            int o2 = off2 + (int)(akv.y & 0xFFFFu);
            int o3 = off3 + (int)(akv.y >> 16);
            int o4 = off4 + (int)(akv.z & 0xFFFFu);
            int o5 = off5 + (int)(akv.z >> 16);
            int o6 = off6 + (int)(akv.w & 0xFFFFu);
            int o7 = off7 + (int)(akv.w >> 16);

            int d = i - j;
            if (d < MAXD) {   // only possible in the last iteration
                o0 += sArD[d * 8 + 0];
                o1 += sArD[d * 8 + 1];
                o2 += sArD[d * 8 + 2];
                o3 += sArD[d * 8 + 3];
                o4 += sArD[d * 8 + 4];
                o5 += sArD[d * 8 + 5];
                o6 += sArD[d * 8 + 6];
                o7 += sArD[d * 8 + 7];
            }

            int v = (int)sTab[o0] + (int)sTab[o1] + (int)sTab[o2] + (int)sTab[o3] +
                    (int)sTab[o4] + (int)sTab[o5] + (int)sTab[o6] + (int)sTab[o7];

            if (v >= HEADS / 2) {
                cnt++;
                uint4 t0 = sTokLo[j];
                uint4 t1 = sTokHi[j];
                a0 ^= t0.x; a1 ^= t0.y; a2 ^= t0.z; a3 ^= t0.w;
                a4 ^= t1.x; a5 ^= t1.y; a6 ^= t1.z; a7 ^= t1.w;
            }
            kmax = max(kmax, (v << 12) | (2047 - j));   // ties -> smallest j
        }

        // warp butterfly: every lane ends with this warp's full partial
        #pragma unroll
        for (int s = 16; s; s >>= 1) {
            a0 ^= __shfl_xor_sync(0xFFFFFFFFu, a0, s);
            a1 ^= __shfl_xor_sync(0xFFFFFFFFu, a1, s);
            a2 ^= __shfl_xor_sync(0xFFFFFFFFu, a2, s);
            a3 ^= __shfl_xor_sync(0xFFFFFFFFu, a3, s);
            a4 ^= __shfl_xor_sync(0xFFFFFFFFu, a4, s);
            a5 ^= __shfl_xor_sync(0xFFFFFFFFu, a5, s);
            a6 ^= __shfl_xor_sync(0xFFFFFFFFu, a6, s);
            a7 ^= __shfl_xor_sync(0xFFFFFFFFu, a7, s);
            cnt  += __shfl_xor_sync(0xFFFFFFFFu, cnt, s);
            kmax  = max(kmax, __shfl_xor_sync(0xFFFFFFFFu, kmax, s));
        }

        // odd warp parks its partial for its even partner
        if (sub == 1 && lane < 10) {
            uint32_t v;
            if (lane == 0) v = a0;
            else if (lane == 1) v = a1;
            else if (lane == 2) v = a2;
            else if (lane == 3) v = a3;
            else if (lane == 4) v = a4;
            else if (lane == 5) v = a5;
            else if (lane == 6) v = a6;
            else if (lane == 7) v = a7;
            else if (lane == 8) v = (uint32_t)cnt;
            else                v = (uint32_t)kmax;
            sRed[wid * 10 + lane] = v;
        }
    }

    __syncthreads();   // single block sync: pair partials are visible

    if (active && sub == 0) {
        const uint32_t* p = sRed + (wid + 1) * 10;   // partner partial (broadcast reads)
        a0 ^= p[0]; a1 ^= p[1]; a2 ^= p[2]; a3 ^= p[3];
        a4 ^= p[4]; a5 ^= p[5]; a6 ^= p[6]; a7 ^= p[7];
        cnt += (int)p[8];
        kmax = max(kmax, (int)p[9]);

        // each lane writes 8 consecutive output bits of row i
        int widx = lane >> 2;                 // which 32-bit word (0..7)
        uint32_t w;
        if (cnt > 0) {
            w = a0;
            if (widx == 1) w = a1;
            if (widx == 2) w = a2;
            if (widx == 3) w = a3;
            if (widx == 4) w = a4;
            if (widx == 5) w = a5;
            if (widx == 6) w = a6;
            if (widx == 7) w = a7;
        } else {
            int aj = 2047 - (kmax & 4095);
            const uint32_t* lo = (const uint32_t*)sTokLo;
            const uint32_t* hi = (const uint32_t*)sTokHi;
            w = (widx < 4) ? lo[aj * 4 + widx] : hi[aj * 4 + (widx - 4)];
        }
        int sh = (lane & 3) * 8;
        float4* o = (float4*)(out + i * BITS + lane * 8);
        o[0] = make_float4((float)((w >> (sh + 0)) & 1u), (float)((w >> (sh + 1)) & 1u),
                           (float)((w >> (sh + 2)) & 1u), (float)((w >> (sh + 3)) & 1u));
        o[1] = make_float4((float)((w >> (sh + 4)) & 1u), (float)((w >> (sh + 5)) & 1u),
                           (float)((w >> (sh + 6)) & 1u), (float)((w >> (sh + 7)) & 1u));
    }
}

extern "C" void kernel_launch(void* const* d_in, const int* in_sizes, int n_in,
                              void* d_out, int out_size) {
    const int*   tokens   = (const int*)d_in[0];
    const int*   head_idx = (const int*)d_in[1];
    const float* table    = (const float*)d_in[2];
    float*       out      = (float*)d_out;

    const int SMEM_BYTES = 131072 + 128 * 4 + 32 * 10 * 4;
    cudaFuncSetAttribute(main_kernel,
                         cudaFuncAttributeMaxDynamicSharedMemorySize, SMEM_BYTES);

    pre_kernel<<<(SEQ * 32 + 255) / 256, 256>>>(tokens, head_idx, table);
    main_kernel<<<GRID_MAIN, NT, SMEM_BYTES>>>(out);
}

// round 6
// speedup vs baseline: 1.2092x; 1.2092x over previous
#include <cuda_runtime.h>
#include <stdint.h>

#define SEQ    2048
#define BITS   256
#define HEADS  8
#define NBPN   12
#define MAXD   8
#define NT     1024
#define GRID_MAIN 152

// Scratch (device globals -- no allocation allowed)
__device__ uint32_t       g_tok[SEQ * 8];          // packed token bits, 32B/row
__device__ unsigned short g_Ak[SEQ * 8];           // per-row key-address parts
__device__ unsigned short g_Aq[SEQ * 8];           // per-row query-address parts
__device__ uint32_t       g_tabBits[HEADS * 128];  // bit-packed table, 4KB
__device__ short          g_Ar[(MAXD + 1) * HEADS];

// ---------------------------------------------------------------------------
// Precompute: ballot-pack table floats into bit words, ballot-pack token bits,
// build Aq/Ak per row, Ar per distance.
// ---------------------------------------------------------------------------
__global__ void pre_kernel(const int* __restrict__ tokens,
                           const int* __restrict__ head_idx,
                           const float* __restrict__ table) {
    int tid = blockIdx.x * blockDim.x + threadIdx.x;
    int lane = tid & 31;

    // bit-pack table: 32768 entries -> 1024 words (warp-uniform ballots)
    if (tid < HEADS * 4096) {
        uint32_t w = __ballot_sync(0xFFFFFFFFu, table[tid] > 0.5f);
        if (lane == 0) g_tabBits[tid >> 5] = w;
    }

    if (tid < (MAXD + 1) * HEADS) {
        int d = tid / HEADS, h = tid % HEADS;
        int ar = 0;
        for (int k = 0; k < NBPN; k++) {
            int idx = head_idx[h * NBPN + k];
            if (idx >= 2 * BITS) {
                int p = idx - 2 * BITS;
                if (p > 3) p = 3;
                ar |= ((d >> p) & 1) << k;
            }
        }
        g_Ar[d * HEADS + h] = (short)ar;
    }

    int row = tid >> 5;
    if (row < SEQ) {
        uint32_t w[8];
        #pragma unroll
        for (int q = 0; q < 8; q++) {
            int v = tokens[row * BITS + q * 32 + lane];
            w[q] = __ballot_sync(0xFFFFFFFFu, v & 1);   // all lanes get the word
        }
        if (lane < 8) {
            g_tok[row * 8 + lane] = w[lane];
            int h = lane;
            int aq = 0, ak = 0;
            for (int k = 0; k < NBPN; k++) {
                int idx = head_idx[h * NBPN + k];
                if (idx < BITS) {
                    aq |= (int)((w[idx >> 5] >> (idx & 31)) & 1u) << k;
                } else if (idx < 2 * BITS) {
                    int i2 = idx - BITS;
                    ak |= (int)((w[i2 >> 5] >> (i2 & 31)) & 1u) << k;
                }
            }
            g_Aq[row * 8 + h] = (unsigned short)aq;
            g_Ak[row * 8 + h] = (unsigned short)ak;
        }
    }
}

// ---------------------------------------------------------------------------
// Main: persistent CTAs, TWO WARPS PER ROW. Table bit-packed and replicated
// once per smem bank -> every table gather is conflict-free (1 wavefront).
// Replica L: word w at byte offset w*128 + L*4  (bank == L for lane L).
// ---------------------------------------------------------------------------
__global__ __launch_bounds__(NT, 1)
void main_kernel(float* __restrict__ out) {
    extern __shared__ unsigned char smem[];
    uint32_t* sRep   = (uint32_t*)smem;                   // 131072 B (32 replicas)
    uint4*    sAk4   = (uint4*)(smem + 131072);           // 32768 B
    uint4*    sTokLo = (uint4*)(smem + 163840);           // 32768 B (words 0..3)
    uint4*    sTokHi = (uint4*)(smem + 196608);           // 32768 B (words 4..7)
    int*      sArD   = (int*)(smem + 229376);             // 72 ints: Ar[d]-Ar[8]
    uint32_t* sRed   = (uint32_t*)(smem + 229664);        // 32 warps x 10

    const int tid = threadIdx.x;
    const int lane = tid & 31, wid = tid >> 5;

    // Stage working set into SMEM once per block
    {
        // bit-table replicas: thread tid owns word tid (NT == 1024 words)
        uint32_t val = g_tabBits[tid];
        #pragma unroll
        for (int r = 0; r < 32; r++) {
            int L = (r + lane) & 31;            // staggered -> conflict-free stores
            sRep[tid * 32 + L] = val;
        }
        const uint4* g2 = (const uint4*)g_Ak;
        for (int x = tid; x < 2048; x += NT) sAk4[x] = g2[x];
        const uint4* g3 = (const uint4*)g_tok;
        for (int x = tid; x < 4096; x += NT) {
            uint4 v = g3[x];
            if (x & 1) sTokHi[x >> 1] = v; else sTokLo[x >> 1] = v;
        }
        if (tid < (MAXD + 1) * HEADS)
            sArD[tid] = (int)g_Ar[tid] - (int)g_Ar[MAXD * HEADS + (tid & 7)];
    }
    __syncthreads();

    const int pair = wid >> 1, sub = wid & 1;
    const int i = pair * GRID_MAIN + (int)blockIdx.x;   // one row per warp PAIR
    const bool active = (i < SEQ);

    uint32_t a0 = 0, a1 = 0, a2 = 0, a3 = 0, a4 = 0, a5 = 0, a6 = 0, a7 = 0;
    int cnt = 0;
    int kmax = -1;

    if (active) {
        // lane-private replica base (bank == lane), in words
        const uint32_t* laneRep = sRep + lane;

        int off0 = 0 * 4096 + (int)g_Aq[i * 8 + 0] + (int)g_Ar[MAXD * HEADS + 0];
        int off1 = 1 * 4096 + (int)g_Aq[i * 8 + 1] + (int)g_Ar[MAXD * HEADS + 1];
        int off2 = 2 * 4096 + (int)g_Aq[i * 8 + 2] + (int)g_Ar[MAXD * HEADS + 2];
        int off3 = 3 * 4096 + (int)g_Aq[i * 8 + 3] + (int)g_Ar[MAXD * HEADS + 3];
        int off4 = 4 * 4096 + (int)g_Aq[i * 8 + 4] + (int)g_Ar[MAXD * HEADS + 4];
        int off5 = 5 * 4096 + (int)g_Aq[i * 8 + 5] + (int)g_Ar[MAXD * HEADS + 5];
        int off6 = 6 * 4096 + (int)g_Aq[i * 8 + 6] + (int)g_Ar[MAXD * HEADS + 6];
        int off7 = 7 * 4096 + (int)g_Aq[i * 8 + 7] + (int)g_Ar[MAXD * HEADS + 7];

        #pragma unroll 2
        for (int j = lane + 32 * sub; j <= i; j += 64) {
            uint4 akv = sAk4[j];
            int o0 = off0 + (int)(akv.x & 0xFFFFu);
            int o1 = off1 + (int)(akv.x >> 16);
            int o2 = off2 + (int)(akv.y & 0xFFFFu);
            int o3 = off3 + (int)(akv.y >> 16);
            int o4 = off4 + (int)(akv.z & 0xFFFFu);
            int o5 = off5 + (int)(akv.z >> 16);
            int o6 = off6 + (int)(akv.w & 0xFFFFu);
            int o7 = off7 + (int)(akv.w >> 16);

            int d = i - j;
            if (d < MAXD) {   // only possible in the last iteration
                o0 += sArD[d * 8 + 0];
                o1 += sArD[d * 8 + 1];
                o2 += sArD[d * 8 + 2];
                o3 += sArD[d * 8 + 3];
                o4 += sArD[d * 8 + 4];
                o5 += sArD[d * 8 + 5];
                o6 += sArD[d * 8 + 6];
                o7 += sArD[d * 8 + 7];
            }

            // conflict-free bit-table gathers: lane reads only its own bank
            int v = (int)((laneRep[(o0 >> 5) * 32] >> (o0 & 31)) & 1u)
                  + (int)((laneRep[(o1 >> 5) * 32] >> (o1 & 31)) & 1u)
                  + (int)((laneRep[(o2 >> 5) * 32] >> (o2 & 31)) & 1u)
                  + (int)((laneRep[(o3 >> 5) * 32] >> (o3 & 31)) & 1u)
                  + (int)((laneRep[(o4 >> 5) * 32] >> (o4 & 31)) & 1u)
                  + (int)((laneRep[(o5 >> 5) * 32] >> (o5 & 31)) & 1u)
                  + (int)((laneRep[(o6 >> 5) * 32] >> (o6 & 31)) & 1u)
                  + (int)((laneRep[(o7 >> 5) * 32] >> (o7 & 31)) & 1u);

            if (v >= HEADS / 2) {
                cnt++;
                uint4 t0 = sTokLo[j];
                uint4 t1 = sTokHi[j];
                a0 ^= t0.x; a1 ^= t0.y; a2 ^= t0.z; a3 ^= t0.w;
                a4 ^= t1.x; a5 ^= t1.y; a6 ^= t1.z; a7 ^= t1.w;
            }
            kmax = max(kmax, (v << 12) | (2047 - j));   // ties -> smallest j
        }

        // warp butterfly: every lane ends with this warp's full partial
        #pragma unroll
        for (int s = 16; s; s >>= 1) {
            a0 ^= __shfl_xor_sync(0xFFFFFFFFu, a0, s);
            a1 ^= __shfl_xor_sync(0xFFFFFFFFu, a1, s);
            a2 ^= __shfl_xor_sync(0xFFFFFFFFu, a2, s);
            a3 ^= __shfl_xor_sync(0xFFFFFFFFu, a3, s);
            a4 ^= __shfl_xor_sync(0xFFFFFFFFu, a4, s);
            a5 ^= __shfl_xor_sync(0xFFFFFFFFu, a5, s);
            a6 ^= __shfl_xor_sync(0xFFFFFFFFu, a6, s);
            a7 ^= __shfl_xor_sync(0xFFFFFFFFu, a7, s);
            cnt  += __shfl_xor_sync(0xFFFFFFFFu, cnt, s);
            kmax  = max(kmax, __shfl_xor_sync(0xFFFFFFFFu, kmax, s));
        }

        // odd warp parks its partial for its even partner
        if (sub == 1 && lane < 10) {
            uint32_t v;
            if (lane == 0) v = a0;
            else if (lane == 1) v = a1;
            else if (lane == 2) v = a2;
            else if (lane == 3) v = a3;
            else if (lane == 4) v = a4;
            else if (lane == 5) v = a5;
            else if (lane == 6) v = a6;
            else if (lane == 7) v = a7;
            else if (lane == 8) v = (uint32_t)cnt;
            else                v = (uint32_t)kmax;
            sRed[wid * 10 + lane] = v;
        }
    }

    __syncthreads();   // single block sync: pair partials are visible

    if (active && sub == 0) {
        const uint32_t* p = sRed + (wid + 1) * 10;   // partner partial
        a0 ^= p[0]; a1 ^= p[1]; a2 ^= p[2]; a3 ^= p[3];
        a4 ^= p[4]; a5 ^= p[5]; a6 ^= p[6]; a7 ^= p[7];
        cnt += (int)p[8];
        kmax = max(kmax, (int)p[9]);

        // each lane writes 8 consecutive output bits of row i
        int widx = lane >> 2;                 // which 32-bit word (0..7)
        uint32_t w;
        if (cnt > 0) {
            w = a0;
            if (widx == 1) w = a1;
            if (widx == 2) w = a2;
            if (widx == 3) w = a3;
            if (widx == 4) w = a4;
            if (widx == 5) w = a5;
            if (widx == 6) w = a6;
            if (widx == 7) w = a7;
        } else {
            int aj = 2047 - (kmax & 4095);
            const uint32_t* lo = (const uint32_t*)sTokLo;
            const uint32_t* hi = (const uint32_t*)sTokHi;
            w = (widx < 4) ? lo[aj * 4 + widx] : hi[aj * 4 + (widx - 4)];
        }
        int sh = (lane & 3) * 8;
        float4* o = (float4*)(out + i * BITS + lane * 8);
        o[0] = make_float4((float)((w >> (sh + 0)) & 1u), (float)((w >> (sh + 1)) & 1u),
                           (float)((w >> (sh + 2)) & 1u), (float)((w >> (sh + 3)) & 1u));
        o[1] = make_float4((float)((w >> (sh + 4)) & 1u), (float)((w >> (sh + 5)) & 1u),
                           (float)((w >> (sh + 6)) & 1u), (float)((w >> (sh + 7)) & 1u));
    }
}

extern "C" void kernel_launch(void* const* d_in, const int* in_sizes, int n_in,
                              void* d_out, int out_size) {
    const int*   tokens   = (const int*)d_in[0];
    const int*   head_idx = (const int*)d_in[1];
    const float* table    = (const float*)d_in[2];
    float*       out      = (float*)d_out;

    const int SMEM_BYTES = 229664 + 32 * 10 * 4;   // 230944 B
    cudaFuncSetAttribute(main_kernel,
                         cudaFuncAttributeMaxDynamicSharedMemorySize, SMEM_BYTES);

    pre_kernel<<<(SEQ * 32 + 255) / 256, 256>>>(tokens, head_idx, table);
    main_kernel<<<GRID_MAIN, NT, SMEM_BYTES>>>(out);
}